// round 1
// baseline (speedup 1.0000x reference)
#include <cuda_runtime.h>
#include <cuda_bf16.h>

typedef unsigned long long ull;

// ---------------- device scratch (no allocations allowed) ----------------
#define MAX_B 8192
__device__ float g_pooled[MAX_B * 128];
__device__ int   g_cumsum[MAX_B];

// ---------------- constants ----------------
#define TILE      96      // nodes per block
#define NPW       12      // nodes per warp
#define XSTRIDE   98      // padded node-stride of transposed smem tiles (even -> 8B aligned ull)
#define RN        128
#define HX        66
#define THREADS   256

#define XS_FLOATS (HX * XSTRIDE)          // 6468
#define WB_FLOATS (RN * RN)               // 16384
#define AT_FLOATS (RN * XSTRIDE)          // 12544
#define SMEM_FLOATS (XS_FLOATS + WB_FLOATS + 2*AT_FLOATS + TILE)   // +maskS
#define SMEM_BYTES ((SMEM_FLOATS + TILE) * 4)                       // + gidx ints

// ---------------- fast math helpers ----------------
__device__ __forceinline__ float fast_ex2(float x) {
    float r; asm("ex2.approx.ftz.f32 %0, %1;" : "=f"(r) : "f"(x)); return r;
}
__device__ __forceinline__ float fast_rcp(float x) {
    float r; asm("rcp.approx.ftz.f32 %0, %1;" : "=f"(r) : "f"(x)); return r;
}
#define L2E 1.4426950408889634f

__device__ __forceinline__ float sigmoid_f(float x) {
    return fast_rcp(1.0f + fast_ex2(-x * L2E));
}
__device__ __forceinline__ float tanh_f(float x) {
    // tanh(x) = 1 - 2/(e^{2x}+1); exact limits at +-inf via ex2 saturation
    return 1.0f - 2.0f * fast_rcp(1.0f + fast_ex2(2.0f * x * L2E));
}
__device__ __forceinline__ float selu_f(float x) {
    float e = fast_ex2(x * L2E);
    float neg = 1.6732632423543772f * (e - 1.0f);
    float v = (x > 0.0f) ? x : neg;
    return 1.0507009873554805f * v;
}

// ---------------- packed fp32x2 helpers (Blackwell FFMA2 path) ----------------
__device__ __forceinline__ ull pack2(float a, float b) {
    ull r; asm("mov.b64 %0, {%1, %2};" : "=l"(r) : "f"(a), "f"(b)); return r;
}
__device__ __forceinline__ float2 unpack2(ull v) {
    float2 f; asm("mov.b64 {%0, %1}, %2;" : "=f"(f.x), "=f"(f.y) : "l"(v)); return f;
}
__device__ __forceinline__ ull ffma2(ull a, ull b, ull c) {
    ull d; asm("fma.rn.f32x2 %0, %1, %2, %3;" : "=l"(d) : "l"(a), "l"(b), "l"(c)); return d;
}

// ---------------- scan: cumsum of n_node ----------------
__global__ void scan_kernel(const int* __restrict__ nn, int B) {
    __shared__ int s[1024];
    int tid = threadIdx.x;
    int per = (B + 1023) >> 10;
    if (per > 8) per = 8;
    int base = tid * per;
    int loc[8];
    int sum = 0;
    for (int e = 0; e < per; e++) {
        int idx = base + e;
        int v = (idx < B) ? nn[idx] : 0;
        loc[e] = v; sum += v;
    }
    s[tid] = sum;
    __syncthreads();
    for (int off = 1; off < 1024; off <<= 1) {
        int v = (tid >= off) ? s[tid - off] : 0;
        __syncthreads();
        s[tid] += v;
        __syncthreads();
    }
    int run = s[tid] - sum;   // exclusive prefix of this thread's chunk
    for (int e = 0; e < per; e++) {
        int idx = base + e;
        if (idx < B) { run += loc[e]; g_cumsum[idx] = run; }  // inclusive cumsum
    }
}

// ---------------- zero pooled ----------------
__global__ void zero_kernel(int count) {
    int i = blockIdx.x * blockDim.x + threadIdx.x;
    if (i < count) g_pooled[i] = 0.0f;
}

// ---------------- fused main kernel ----------------
__device__ __forceinline__ void load_wbuf(float* __restrict__ Wbuf,
                                          const float* __restrict__ w, int kdim) {
    int n4 = kdim * (RN / 4);
    for (int i = threadIdx.x; i < n4; i += THREADS)
        ((float4*)Wbuf)[i] = ((const float4*)w)[i];
}

__device__ __forceinline__ void init_acc(ull acc[6][4], const float* __restrict__ b, int tc) {
    float4 bv = *(const float4*)(b + (tc << 2));
    ull b0 = pack2(bv.x, bv.x), b1 = pack2(bv.y, bv.y);
    ull b2 = pack2(bv.z, bv.z), b3 = pack2(bv.w, bv.w);
#pragma unroll
    for (int p = 0; p < 6; p++) { acc[p][0] = b0; acc[p][1] = b1; acc[p][2] = b2; acc[p][3] = b3; }
}

template <int KDIM>
__device__ __forceinline__ void gemm_tile(const float* __restrict__ xT,
                                          const float* __restrict__ Wb,
                                          ull acc[6][4], int w, int tc) {
#pragma unroll 2
    for (int k = 0; k < KDIM; k++) {
        const float* xr = xT + k * XSTRIDE + w * NPW;
        ull x[6];
#pragma unroll
        for (int p = 0; p < 6; p++) x[p] = *(const ull*)(xr + 2 * p);
        float4 wv = *(const float4*)(Wb + k * RN + (tc << 2));
        ull w0 = pack2(wv.x, wv.x), w1 = pack2(wv.y, wv.y);
        ull w2 = pack2(wv.z, wv.z), w3 = pack2(wv.w, wv.w);
#pragma unroll
        for (int p = 0; p < 6; p++) {
            acc[p][0] = ffma2(x[p], w0, acc[p][0]);
            acc[p][1] = ffma2(x[p], w1, acc[p][1]);
            acc[p][2] = ffma2(x[p], w2, acc[p][2]);
            acc[p][3] = ffma2(x[p], w3, acc[p][3]);
        }
    }
}

// ACT: 0 = none, 1 = tanh, 2 = selu
template <int ACT>
__device__ __forceinline__ void store_tile(ull acc[6][4], float* __restrict__ dst, int w, int tc) {
#pragma unroll
    for (int q = 0; q < 4; q++) {
        int c = (tc << 2) + q;
#pragma unroll
        for (int p = 0; p < 6; p++) {
            float2 v = unpack2(acc[p][q]);
            if (ACT == 1) { v.x = tanh_f(v.x); v.y = tanh_f(v.y); }
            if (ACT == 2) { v.x = selu_f(v.x); v.y = selu_f(v.y); }
            *(ull*)&dst[c * XSTRIDE + w * NPW + 2 * p] = pack2(v.x, v.y);
        }
    }
}

__global__ void __launch_bounds__(THREADS, 1)
fused_kernel(const float* __restrict__ nodes, const float* __restrict__ nmask,
             const float* __restrict__ i1w, const float* __restrict__ i1b,
             const float* __restrict__ i2w, const float* __restrict__ i2b,
             const float* __restrict__ j1w, const float* __restrict__ j1b,
             const float* __restrict__ j2w, const float* __restrict__ j2b,
             int N, int B) {
    extern __shared__ float sm[];
    float* XsT   = sm;                         // [66][98]  (transposed hx tile)
    float* Wbuf  = XsT + XS_FLOATS;            // [128][128]
    float* AT    = Wbuf + WB_FLOATS;           // [128][98] (transposed activations)
    float* IT    = AT + AT_FLOATS;             // [128][98] (i-branch layer-2 result)
    float* maskS = IT + AT_FLOATS;             // [96]
    int*   gidxS = (int*)(maskS + TILE);       // [96]

    int tid = threadIdx.x;
    int w = tid >> 5, tc = tid & 31;
    int n0 = blockIdx.x * TILE;

    // Load hx tile, transposed: XsT[c][n]. cols 64,65 replicate cols 0,1.
    for (int idx = tid; idx < TILE * HX; idx += THREADS) {
        int n = idx / HX, c = idx - n * HX;
        int gn = n0 + n;
        float v = 0.0f;
        if (gn < N) {
            int cc = (c < 64) ? c : (c - 64);
            v = nodes[gn * 64 + cc];
        }
        XsT[c * XSTRIDE + n] = v;
    }
    if (tid < TILE) {
        int gn = n0 + tid;
        maskS[tid] = (gn < N) ? nmask[gn] : 0.0f;
        // graph index: smallest g with gn < cumsum[g]; >= total -> B-1 (repeat pad semantics)
        int lo = 0, hi = B - 1;
        while (lo < hi) {
            int mid = (lo + hi) >> 1;
            if (gn < g_cumsum[mid]) hi = mid; else lo = mid + 1;
        }
        gidxS[tid] = lo;
    }
    load_wbuf(Wbuf, i1w, HX);
    __syncthreads();

    ull acc[6][4];

    // ---- i branch, layer 1: tanh(hx @ i1w + i1b) ----
    init_acc(acc, i1b, tc);
    gemm_tile<HX>(XsT, Wbuf, acc, w, tc);
    store_tile<1>(acc, AT, w, tc);
    __syncthreads();
    load_wbuf(Wbuf, i2w, RN);
    __syncthreads();

    // ---- i branch, layer 2 -> IT ----
    init_acc(acc, i2b, tc);
    gemm_tile<RN>(AT, Wbuf, acc, w, tc);
    store_tile<0>(acc, IT, w, tc);
    __syncthreads();
    load_wbuf(Wbuf, j1w, HX);
    __syncthreads();

    // ---- j branch, layer 1: selu(hx @ j1w + j1b) ----
    init_acc(acc, j1b, tc);
    gemm_tile<HX>(XsT, Wbuf, acc, w, tc);
    store_tile<2>(acc, AT, w, tc);
    __syncthreads();
    load_wbuf(Wbuf, j2w, RN);
    __syncthreads();

    // ---- j branch, layer 2 (kept in regs) + gate + mask + segmented col-sum ----
    init_acc(acc, j2b, tc);
    gemm_tile<RN>(AT, Wbuf, acc, w, tc);

    int nb = w * NPW;
#pragma unroll
    for (int q = 0; q < 4; q++) {
        int c = (tc << 2) + q;
        float cs = 0.0f;
        int gcur = gidxS[nb];
#pragma unroll
        for (int p = 0; p < 6; p++) {
            float2 jv = unpack2(acc[p][q]);
            float2 iv = unpack2(*(const ull*)&IT[c * XSTRIDE + nb + 2 * p]);
            float r0 = sigmoid_f(iv.x) * jv.x * maskS[nb + 2 * p];
            float r1 = sigmoid_f(iv.y) * jv.y * maskS[nb + 2 * p + 1];
            int g0 = gidxS[nb + 2 * p];
            int g1 = gidxS[nb + 2 * p + 1];
            if (g0 != gcur) { atomicAdd(&g_pooled[gcur * RN + c], cs); cs = 0.0f; gcur = g0; }
            cs += r0;
            if (g1 != gcur) { atomicAdd(&g_pooled[gcur * RN + c], cs); cs = 0.0f; gcur = g1; }
            cs += r1;
        }
        atomicAdd(&g_pooled[gcur * RN + c], cs);
    }
}

// ---------------- final per-graph MLP: selu(pooled @ h1 + b1) @ h2 + b2 ----------------
__global__ void final_kernel(const float* __restrict__ h1w, const float* __restrict__ h1b,
                             const float* __restrict__ h2w, const float* __restrict__ h2b,
                             float* __restrict__ out, int B) {
    int g = blockIdx.x * (blockDim.x >> 5) + (threadIdx.x >> 5);
    int lane = threadIdx.x & 31;
    if (g >= B) return;
    const float* pr = &g_pooled[g * RN];
    float4 bv = ((const float4*)h1b)[lane];
    float a0 = bv.x, a1 = bv.y, a2 = bv.z, a3 = bv.w;
#pragma unroll 4
    for (int k = 0; k < RN; k++) {
        float pv = pr[k];
        float4 wv = *(const float4*)(h1w + k * RN + (lane << 2));
        a0 = fmaf(pv, wv.x, a0);
        a1 = fmaf(pv, wv.y, a1);
        a2 = fmaf(pv, wv.z, a2);
        a3 = fmaf(pv, wv.w, a3);
    }
    a0 = selu_f(a0); a1 = selu_f(a1); a2 = selu_f(a2); a3 = selu_f(a3);
    float4 h2 = ((const float4*)h2w)[lane];
    float part = a0 * h2.x + a1 * h2.y + a2 * h2.z + a3 * h2.w;
#pragma unroll
    for (int off = 16; off > 0; off >>= 1)
        part += __shfl_down_sync(0xffffffffu, part, off);
    if (lane == 0) out[g] = part + h2b[0];
}

// ---------------- launch ----------------
extern "C" void kernel_launch(void* const* d_in, const int* in_sizes, int n_in,
                              void* d_out, int out_size) {
    const float* nodes = (const float*)d_in[0];
    const float* nmask = (const float*)d_in[1];
    const int*   n_node = (const int*)d_in[2];
    const float* i1w = (const float*)d_in[3];
    const float* i1b = (const float*)d_in[4];
    const float* i2w = (const float*)d_in[5];
    const float* i2b = (const float*)d_in[6];
    const float* j1w = (const float*)d_in[7];
    const float* j1b = (const float*)d_in[8];
    const float* j2w = (const float*)d_in[9];
    const float* j2b = (const float*)d_in[10];
    const float* h1w = (const float*)d_in[11];
    const float* h1b = (const float*)d_in[12];
    const float* h2w = (const float*)d_in[13];
    const float* h2b = (const float*)d_in[14];

    int N = in_sizes[1];   // node_mask has N elements
    int B = in_sizes[2];   // n_node has B elements

    scan_kernel<<<1, 1024>>>(n_node, B);

    int pc = B * RN;
    zero_kernel<<<(pc + 255) / 256, 256>>>(pc);

    cudaFuncSetAttribute(fused_kernel, cudaFuncAttributeMaxDynamicSharedMemorySize,
                         (int)SMEM_BYTES);
    int grid = (N + TILE - 1) / TILE;
    fused_kernel<<<grid, THREADS, SMEM_BYTES>>>(nodes, nmask,
                                                i1w, i1b, i2w, i2b,
                                                j1w, j1b, j2w, j2b, N, B);

    final_kernel<<<(B + 7) / 8, 256>>>(h1w, h1b, h2w, h2b, (float*)d_out, B);
}

// round 3
// speedup vs baseline: 1.7681x; 1.7681x over previous
#include <cuda_runtime.h>
#include <cuda_bf16.h>
#include <cstdint>

// ============================ device scratch ============================
#define MAX_B 8192
__device__ float g_pooled[MAX_B * 128];
__device__ int   g_cumsum[MAX_B];
// pre-transposed bf16 weight images Wt[n][k], hi/lo: [layer][half][128*136]
__device__ __nv_bfloat16 g_wimg[4][2][128 * 136];

// ============================ constants ============================
#define RN       128
#define TILE_M   128
#define THREADS  256

#define K1       80     // layer-1 K (66 padded to 80)
#define KST1     88     // bf16 stride (176B rows: ldmatrix conflict-free)
#define KSTEPS1  5
#define K2       128
#define KST2     136    // 272B rows: conflict-free
#define KSTEPS2  8
#define I2ST     132    // f32 stride for i2out / RR tile

// smem byte offsets
#define HX_HALF  (128 * KST1 * 2)            // 22528
#define OFF_HX   0
#define ACT_HALF (128 * KST2 * 2)            // 34816
#define OFF_ACT  (2 * HX_HALF)               // 45056
#define OFF_W    (OFF_ACT + 2 * ACT_HALF)    // 114688 (single half at a time)
#define OFF_I2   (OFF_W + ACT_HALF)          // 149504
#define I2_BYTES (128 * I2ST * 4)            // 67584
#define OFF_BIAS (OFF_I2 + I2_BYTES)         // 217088 : 4*128 f32
#define OFF_GIDX (OFF_BIAS + 2048)           // 219136 : 128 ints
#define OFF_MASK (OFF_GIDX + 512)            // 219648 : 128 f32
#define SMEM_SZ  (OFF_MASK + 512)            // 220160

// ============================ ptx helpers ============================
__device__ __forceinline__ uint32_t smem_u32(const void* p) {
    uint32_t a;
    asm("{ .reg .u64 t; cvta.to.shared.u64 t, %1; cvt.u32.u64 %0, t; }" : "=r"(a) : "l"(p));
    return a;
}
__device__ __forceinline__ void ldsm4(uint32_t r[4], uint32_t a) {
    asm volatile("ldmatrix.sync.aligned.m8n8.x4.shared.b16 {%0,%1,%2,%3}, [%4];"
                 : "=r"(r[0]), "=r"(r[1]), "=r"(r[2]), "=r"(r[3]) : "r"(a));
}
__device__ __forceinline__ void mma16816(float c[4], const uint32_t a[4], uint32_t b0, uint32_t b1) {
    asm volatile(
        "mma.sync.aligned.m16n8k16.row.col.f32.bf16.bf16.f32 "
        "{%0,%1,%2,%3}, {%4,%5,%6,%7}, {%8,%9}, {%0,%1,%2,%3};"
        : "+f"(c[0]), "+f"(c[1]), "+f"(c[2]), "+f"(c[3])
        : "r"(a[0]), "r"(a[1]), "r"(a[2]), "r"(a[3]), "r"(b0), "r"(b1));
}

// ============================ math helpers ============================
__device__ __forceinline__ float fast_ex2(float x) { float r; asm("ex2.approx.ftz.f32 %0, %1;" : "=f"(r) : "f"(x)); return r; }
__device__ __forceinline__ float fast_rcp(float x) { float r; asm("rcp.approx.ftz.f32 %0, %1;" : "=f"(r) : "f"(x)); return r; }
#define L2E 1.4426950408889634f
__device__ __forceinline__ float sigmoid_f(float x) { return fast_rcp(1.0f + fast_ex2(-x * L2E)); }
__device__ __forceinline__ float tanh_f(float x)    { return 1.0f - 2.0f * fast_rcp(1.0f + fast_ex2(2.0f * x * L2E)); }
__device__ __forceinline__ float selu_f(float x) {
    float e = fast_ex2(x * L2E);
    float neg = 1.6732632423543772f * (e - 1.0f);
    return 1.0507009873554805f * ((x > 0.0f) ? x : neg);
}
// pack two f32 -> bf16x2 (e0 low, e1 high)
__device__ __forceinline__ uint32_t pkbf2(float e0, float e1) {
    uint32_t r; asm("cvt.rn.bf16x2.f32 %0, %1, %2;" : "=r"(r) : "f"(e1), "f"(e0)); return r;
}
// quantize pair -> hi/lo bf16x2, store at byte offsets
__device__ __forceinline__ void qpair_store(char* hiB, char* loB, int elemOff, float e0, float e1) {
    uint32_t h = pkbf2(e0, e1);
    float f0 = __uint_as_float(h << 16);
    float f1 = __uint_as_float(h & 0xffff0000u);
    uint32_t l = pkbf2(e0 - f0, e1 - f1);
    *(uint32_t*)(hiB + elemOff * 2) = h;
    *(uint32_t*)(loB + elemOff * 2) = l;
}

// ============================ prologue kernels ============================
__global__ void scan_kernel(const int* __restrict__ nn, int B) {
    __shared__ int s[1024];
    int tid = threadIdx.x;
    int per = (B + 1023) >> 10;
    if (per > 8) per = 8;
    int base = tid * per;
    int loc[8];
    int sum = 0;
    for (int e = 0; e < per; e++) {
        int idx = base + e;
        int v = (idx < B) ? nn[idx] : 0;
        loc[e] = v; sum += v;
    }
    s[tid] = sum;
    __syncthreads();
    for (int off = 1; off < 1024; off <<= 1) {
        int v = (tid >= off) ? s[tid - off] : 0;
        __syncthreads();
        s[tid] += v;
        __syncthreads();
    }
    int run = s[tid] - sum;
    for (int e = 0; e < per; e++) {
        int idx = base + e;
        if (idx < B) { run += loc[e]; g_cumsum[idx] = run; }
    }
}

__global__ void zero_kernel(int count) {
    int i = blockIdx.x * blockDim.x + threadIdx.x;
    if (i < count) g_pooled[i] = 0.0f;
}

// Wt[n][k] = W[k][n], k < kpad (zero-pad), hi/lo split
__global__ void quant_w_kernel(const float* __restrict__ w, int kact, int kpad, int stride, int layer) {
    int idx = blockIdx.x * blockDim.x + threadIdx.x;
    if (idx >= 128 * kpad) return;
    int n = idx / kpad, k = idx - n * kpad;
    float v = (k < kact) ? w[k * 128 + n] : 0.0f;
    __nv_bfloat16 hb = __float2bfloat16(v);
    float fh = __bfloat162float(hb);
    __nv_bfloat16 lb = __float2bfloat16(v - fh);
    g_wimg[layer][0][n * stride + k] = hb;
    g_wimg[layer][1][n * stride + k] = lb;
}

// ============================ gemm pieces ============================
__device__ __forceinline__ void copy_w(char* sm, int layer, int half, int bytes) {
    const uint4* src = (const uint4*)&g_wimg[layer][half][0];
    uint4* dst = (uint4*)(sm + OFF_W);
    int n16 = bytes >> 4;
    for (int i = threadIdx.x; i < n16; i += THREADS) dst[i] = src[i];
}

__device__ __forceinline__ void zero_acc(float acc[2][8][4]) {
#pragma unroll
    for (int a = 0; a < 2; a++)
#pragma unroll
        for (int b = 0; b < 8; b++)
#pragma unroll
            for (int c = 0; c < 4; c++) acc[a][b][c] = 0.0f;
}

template <int KSTEPS, int KST>
__device__ __forceinline__ void gemm_pass(uint32_t aBase, uint32_t wBase,
                                          float acc[2][8][4], int wm, int wn, int lane) {
    uint32_t aAddr = aBase + (uint32_t)(((wm * 32 + (lane & 15)) * KST + 8 * (lane >> 4)) * 2);
    uint32_t bAddr = wBase + (uint32_t)(((wn * 64 + (lane & 7) + 8 * (lane >> 4)) * KST
                                         + 8 * ((lane >> 3) & 1)) * 2);
#pragma unroll
    for (int ks = 0; ks < KSTEPS; ks++) {
        uint32_t a0[4], a1[4], b[4][4];
        ldsm4(a0, aAddr);
        ldsm4(a1, aAddr + 16 * KST * 2);
#pragma unroll
        for (int g = 0; g < 4; g++) ldsm4(b[g], bAddr + g * (16 * KST * 2));
        aAddr += 32; bAddr += 32;
#pragma unroll
        for (int g = 0; g < 4; g++) {
            mma16816(acc[0][2 * g],     a0, b[g][0], b[g][1]);
            mma16816(acc[0][2 * g + 1], a0, b[g][2], b[g][3]);
            mma16816(acc[1][2 * g],     a1, b[g][0], b[g][1]);
            mma16816(acc[1][2 * g + 1], a1, b[g][2], b[g][3]);
        }
    }
}

// ACT 1 = tanh, 2 = selu: bias + act + hi/lo quantize into act tile (stride KST2)
template <int ACT>
__device__ __forceinline__ void epilogue_act(float acc[2][8][4], char* sm, int biasIdx,
                                             int wm, int wn, int lane) {
    const float* bias = (const float*)(sm + OFF_BIAS) + biasIdx * 128;
    char* hiB = sm + OFF_ACT;
    char* loB = hiB + ACT_HALF;
    int mb = wm * 32 + (lane >> 2);
#pragma unroll
    for (int nt = 0; nt < 8; nt++) {
        int n = wn * 64 + nt * 8 + 2 * (lane & 3);
        float2 bv = *(const float2*)&bias[n];
#pragma unroll
        for (int mt = 0; mt < 2; mt++)
#pragma unroll
            for (int half = 0; half < 2; half++) {
                int m = mb + mt * 16 + half * 8;
                float x0 = acc[mt][nt][2 * half]     + bv.x;
                float x1 = acc[mt][nt][2 * half + 1] + bv.y;
                x0 = (ACT == 1) ? tanh_f(x0) : selu_f(x0);
                x1 = (ACT == 1) ? tanh_f(x1) : selu_f(x1);
                qpair_store(hiB, loB, m * KST2 + n, x0, x1);
            }
    }
}

// store i2 linear output (+bias) as f32 into i2 tile
__device__ __forceinline__ void epilogue_i2(float acc[2][8][4], char* sm, int wm, int wn, int lane) {
    const float* bias = (const float*)(sm + OFF_BIAS) + 1 * 128;
    float* i2 = (float*)(sm + OFF_I2);
    int mb = wm * 32 + (lane >> 2);
#pragma unroll
    for (int nt = 0; nt < 8; nt++) {
        int n = wn * 64 + nt * 8 + 2 * (lane & 3);
        float2 bv = *(const float2*)&bias[n];
#pragma unroll
        for (int mt = 0; mt < 2; mt++)
#pragma unroll
            for (int half = 0; half < 2; half++) {
                int m = mb + mt * 16 + half * 8;
                float2 o;
                o.x = acc[mt][nt][2 * half]     + bv.x;
                o.y = acc[mt][nt][2 * half + 1] + bv.y;
                *(float2*)&i2[m * I2ST + n] = o;
            }
    }
}

// gate: RR = sigmoid(i2) * (j2 + bias) * mask, written over the i2 tile
__device__ __forceinline__ void epilogue_gate(float acc[2][8][4], char* sm, int wm, int wn, int lane) {
    const float* bias  = (const float*)(sm + OFF_BIAS) + 3 * 128;
    const float* maskS = (const float*)(sm + OFF_MASK);
    float* i2 = (float*)(sm + OFF_I2);
    int mb = wm * 32 + (lane >> 2);
#pragma unroll
    for (int nt = 0; nt < 8; nt++) {
        int n = wn * 64 + nt * 8 + 2 * (lane & 3);
        float2 bv = *(const float2*)&bias[n];
#pragma unroll
        for (int mt = 0; mt < 2; mt++)
#pragma unroll
            for (int half = 0; half < 2; half++) {
                int m = mb + mt * 16 + half * 8;
                float mk = maskS[m];
                float2 iv = *(const float2*)&i2[m * I2ST + n];
                float2 o;
                o.x = sigmoid_f(iv.x) * (acc[mt][nt][2 * half]     + bv.x) * mk;
                o.y = sigmoid_f(iv.y) * (acc[mt][nt][2 * half + 1] + bv.y) * mk;
                *(float2*)&i2[m * I2ST + n] = o;
            }
    }
}

// ============================ fused main kernel ============================
__global__ void __launch_bounds__(THREADS, 1)
fused_kernel(const float* __restrict__ nodes, const float* __restrict__ nmask,
             const float* __restrict__ i1b, const float* __restrict__ i2b,
             const float* __restrict__ j1b, const float* __restrict__ j2b,
             int N, int B) {
    extern __shared__ char sm[];
    int tid = threadIdx.x;
    int lane = tid & 31, wid = tid >> 5;
    int wm = wid & 3, wn = wid >> 2;

    float* biasS = (float*)(sm + OFF_BIAS);
    int*   gidxS = (int*)(sm + OFF_GIDX);
    float* maskS = (float*)(sm + OFF_MASK);

    // biases
    for (int i = tid; i < 512; i += THREADS) {
        const float* bp = (i < 128) ? i1b : (i < 256) ? i2b : (i < 384) ? j1b : j2b;
        biasS[i] = bp[i & 127];
    }
    // mask + graph index
    if (tid < 128) {
        int gn = blockIdx.x * TILE_M + tid;
        maskS[tid] = (gn < N) ? nmask[gn] : 0.0f;
        int lo = 0, hi = B - 1;
        while (lo < hi) {
            int mid = (lo + hi) >> 1;
            if (gn < g_cumsum[mid]) hi = mid; else lo = mid + 1;
        }
        gidxS[tid] = lo;
    }

    // ---- load + quantize hx tile [128 x 80] (hi/lo) ----
    {
        int m = tid & 127, h = tid >> 7;
        int gn = blockIdx.x * TILE_M + m;
        char* hiB = sm + OFF_HX;
        char* loB = hiB + HX_HALF;
        float xv[32];
        if (gn < N) {
#pragma unroll
            for (int q = 0; q < 8; q++)
                ((float4*)xv)[q] = *(const float4*)&nodes[(size_t)gn * 64 + h * 32 + q * 4];
        } else {
#pragma unroll
            for (int i = 0; i < 32; i++) xv[i] = 0.0f;
        }
#pragma unroll
        for (int p = 0; p < 16; p++)
            qpair_store(hiB, loB, m * KST1 + h * 32 + 2 * p, xv[2 * p], xv[2 * p + 1]);
        if (h == 1) {
            float e0 = 0.0f, e1 = 0.0f;
            if (gn < N) { e0 = nodes[(size_t)gn * 64]; e1 = nodes[(size_t)gn * 64 + 1]; }
            qpair_store(hiB, loB, m * KST1 + 64, e0, e1);
#pragma unroll
            for (int k = 66; k < 80; k += 2)
                qpair_store(hiB, loB, m * KST1 + k, 0.0f, 0.0f);
        }
    }

    uint32_t sb = smem_u32(sm);
    uint32_t hxHi = sb + OFF_HX, hxLo = hxHi + HX_HALF;
    uint32_t acHi = sb + OFF_ACT, acLo = acHi + ACT_HALF;
    uint32_t wB = sb + OFF_W;

    float acc[2][8][4];

    // ================= G1: i layer-1 (hx @ i1w), tanh =================
    copy_w(sm, 0, 0, HX_HALF);
    __syncthreads();
    zero_acc(acc);
    gemm_pass<KSTEPS1, KST1>(hxHi, wB, acc, wm, wn, lane);  // Ah*Wh
    gemm_pass<KSTEPS1, KST1>(hxLo, wB, acc, wm, wn, lane);  // Al*Wh
    __syncthreads();
    copy_w(sm, 0, 1, HX_HALF);
    __syncthreads();
    gemm_pass<KSTEPS1, KST1>(hxHi, wB, acc, wm, wn, lane);  // Ah*Wl
    epilogue_act<1>(acc, sm, 0, wm, wn, lane);
    __syncthreads();

    // ================= G2: i layer-2 (act @ i2w) -> i2out f32 =================
    copy_w(sm, 1, 0, ACT_HALF);
    __syncthreads();
    zero_acc(acc);
    gemm_pass<KSTEPS2, KST2>(acHi, wB, acc, wm, wn, lane);
    gemm_pass<KSTEPS2, KST2>(acLo, wB, acc, wm, wn, lane);
    __syncthreads();
    copy_w(sm, 1, 1, ACT_HALF);
    __syncthreads();
    gemm_pass<KSTEPS2, KST2>(acHi, wB, acc, wm, wn, lane);
    epilogue_i2(acc, sm, wm, wn, lane);
    __syncthreads();

    // ================= G3: j layer-1 (hx @ j1w), selu =================
    copy_w(sm, 2, 0, HX_HALF);
    __syncthreads();
    zero_acc(acc);
    gemm_pass<KSTEPS1, KST1>(hxHi, wB, acc, wm, wn, lane);
    gemm_pass<KSTEPS1, KST1>(hxLo, wB, acc, wm, wn, lane);
    __syncthreads();
    copy_w(sm, 2, 1, HX_HALF);
    __syncthreads();
    gemm_pass<KSTEPS1, KST1>(hxHi, wB, acc, wm, wn, lane);
    epilogue_act<2>(acc, sm, 2, wm, wn, lane);
    __syncthreads();

    // ================= G4: j layer-2 (act @ j2w) + gate =================
    copy_w(sm, 3, 0, ACT_HALF);
    __syncthreads();
    zero_acc(acc);
    gemm_pass<KSTEPS2, KST2>(acHi, wB, acc, wm, wn, lane);
    gemm_pass<KSTEPS2, KST2>(acLo, wB, acc, wm, wn, lane);
    __syncthreads();
    copy_w(sm, 3, 1, ACT_HALF);
    __syncthreads();
    gemm_pass<KSTEPS2, KST2>(acHi, wB, acc, wm, wn, lane);
    epilogue_gate(acc, sm, wm, wn, lane);
    __syncthreads();

    // ================= segmented column sum -> atomicAdd =================
    {
        const float* RR = (const float*)(sm + OFF_I2);
        int c = tid & 127;
        int h = tid >> 7;
        int m0 = h * 64;
        float cs = 0.0f;
        int gcur = gidxS[m0];
        for (int mm = m0; mm < m0 + 64; mm++) {
            float r = RR[mm * I2ST + c];
            int g = gidxS[mm];
            if (g != gcur) { atomicAdd(&g_pooled[gcur * RN + c], cs); cs = 0.0f; gcur = g; }
            cs += r;
        }
        atomicAdd(&g_pooled[gcur * RN + c], cs);
    }
}

// ============================ final per-graph MLP ============================
__global__ void final_kernel(const float* __restrict__ h1w, const float* __restrict__ h1b,
                             const float* __restrict__ h2w, const float* __restrict__ h2b,
                             float* __restrict__ out, int B) {
    int g = blockIdx.x * (blockDim.x >> 5) + (threadIdx.x >> 5);
    int lane = threadIdx.x & 31;
    if (g >= B) return;
    const float* pr = &g_pooled[g * RN];
    float4 bv = ((const float4*)h1b)[lane];
    float a0 = bv.x, a1 = bv.y, a2 = bv.z, a3 = bv.w;
#pragma unroll 4
    for (int k = 0; k < RN; k++) {
        float pv = pr[k];
        float4 wv = *(const float4*)(h1w + k * RN + (lane << 2));
        a0 = fmaf(pv, wv.x, a0);
        a1 = fmaf(pv, wv.y, a1);
        a2 = fmaf(pv, wv.z, a2);
        a3 = fmaf(pv, wv.w, a3);
    }
    a0 = selu_f(a0); a1 = selu_f(a1); a2 = selu_f(a2); a3 = selu_f(a3);
    float4 h2 = ((const float4*)h2w)[lane];
    float part = a0 * h2.x + a1 * h2.y + a2 * h2.z + a3 * h2.w;
#pragma unroll
    for (int off = 16; off > 0; off >>= 1)
        part += __shfl_down_sync(0xffffffffu, part, off);
    if (lane == 0) out[g] = part + h2b[0];
}

// ============================ launch ============================
extern "C" void kernel_launch(void* const* d_in, const int* in_sizes, int n_in,
                              void* d_out, int out_size) {
    const float* nodes = (const float*)d_in[0];
    const float* nmask = (const float*)d_in[1];
    const int*   n_node = (const int*)d_in[2];
    const float* i1w = (const float*)d_in[3];
    const float* i1b = (const float*)d_in[4];
    const float* i2w = (const float*)d_in[5];
    const float* i2b = (const float*)d_in[6];
    const float* j1w = (const float*)d_in[7];
    const float* j1b = (const float*)d_in[8];
    const float* j2w = (const float*)d_in[9];
    const float* j2b = (const float*)d_in[10];
    const float* h1w = (const float*)d_in[11];
    const float* h1b = (const float*)d_in[12];
    const float* h2w = (const float*)d_in[13];
    const float* h2b = (const float*)d_in[14];

    int N = in_sizes[1];   // node_mask element count
    int B = in_sizes[2];   // n_node element count

    scan_kernel<<<1, 1024>>>(n_node, B);

    int pc = B * RN;
    zero_kernel<<<(pc + 255) / 256, 256>>>(pc);

    // weight images: layer 0=i1 (K80), 1=i2 (K128), 2=j1 (K80), 3=j2 (K128)
    quant_w_kernel<<<(128 * 80 + 255) / 256, 256>>>(i1w, 66, 80, KST1, 0);
    quant_w_kernel<<<(128 * 128 + 255) / 256, 256>>>(i2w, 128, 128, KST2, 1);
    quant_w_kernel<<<(128 * 80 + 255) / 256, 256>>>(j1w, 66, 80, KST1, 2);
    quant_w_kernel<<<(128 * 128 + 255) / 256, 256>>>(j2w, 128, 128, KST2, 3);

    cudaFuncSetAttribute(fused_kernel, cudaFuncAttributeMaxDynamicSharedMemorySize, SMEM_SZ);
    int grid = (N + TILE_M - 1) / TILE_M;
    fused_kernel<<<grid, THREADS, SMEM_SZ>>>(nodes, nmask, i1b, i2b, j1b, j2b, N, B);

    final_kernel<<<(B + 7) / 8, 256>>>(h1w, h1b, h2w, h2b, (float*)d_out, B);
}

// round 4
// speedup vs baseline: 2.6923x; 1.5227x over previous
#include <cuda_runtime.h>
#include <cuda_bf16.h>
#include <cstdint>

// ============================ device scratch ============================
#define MAX_B 8192
__device__ float g_pooled[MAX_B * 128];
__device__ int   g_cumsum[MAX_B];
// pre-transposed bf16 weight images Wt[n][k], hi/lo: [layer][half][128*136]
__device__ __align__(16) __nv_bfloat16 g_wimg[4][2][128 * 136];

// ============================ constants ============================
#define RN       128
#define TILE_M   128
#define THREADS  256

#define KST1     88     // bf16 stride for K=80 tiles (176B rows)
#define KSTEPS1  5
#define KST2     136    // bf16 stride for K=128 tiles (272B rows)
#define KSTEPS2  8
#define I2ST     132    // f32 stride for RR overlay

#define W1_BYTES (128 * KST1 * 2)   // 22528 (one half, K80 layer)
#define W2_BYTES (128 * KST2 * 2)   // 34816 (one half, K128 layer)

// smem byte offsets
#define HX_HALF  (128 * KST1 * 2)            // 22528
#define OFF_HX   0                            // hi + lo = 45056
#define ACT_HALF (128 * KST2 * 2)            // 34816
#define OFF_ACT  (2 * HX_HALF)               // 45056 ; hi+lo = 69632 (RR overlays this)
#define OFF_W0   (OFF_ACT + 2 * ACT_HALF)    // 114688
#define OFF_W1   (OFF_W0 + W2_BYTES)         // 149504
#define OFF_BIAS (OFF_W1 + W2_BYTES)         // 184320 : 4*128 f32
#define OFF_GIDX (OFF_BIAS + 2048)           // 186368 : 128 ints
#define OFF_MASK (OFF_GIDX + 512)            // 186880 : 128 f32
#define SMEM_SZ  (OFF_MASK + 512)            // 187392

// ============================ ptx helpers ============================
__device__ __forceinline__ uint32_t smem_u32(const void* p) {
    uint32_t a;
    asm("{ .reg .u64 t; cvta.to.shared.u64 t, %1; cvt.u32.u64 %0, t; }" : "=r"(a) : "l"(p));
    return a;
}
__device__ __forceinline__ void ldsm4(uint32_t r[4], uint32_t a) {
    asm volatile("ldmatrix.sync.aligned.m8n8.x4.shared.b16 {%0,%1,%2,%3}, [%4];"
                 : "=r"(r[0]), "=r"(r[1]), "=r"(r[2]), "=r"(r[3]) : "r"(a));
}
__device__ __forceinline__ void mma16816(float c[4], const uint32_t a[4], uint32_t b0, uint32_t b1) {
    asm volatile(
        "mma.sync.aligned.m16n8k16.row.col.f32.bf16.bf16.f32 "
        "{%0,%1,%2,%3}, {%4,%5,%6,%7}, {%8,%9}, {%0,%1,%2,%3};"
        : "+f"(c[0]), "+f"(c[1]), "+f"(c[2]), "+f"(c[3])
        : "r"(a[0]), "r"(a[1]), "r"(a[2]), "r"(a[3]), "r"(b0), "r"(b1));
}
__device__ __forceinline__ void cp16(uint32_t dst, const void* src) {
    asm volatile("cp.async.cg.shared.global [%0], [%1], 16;" :: "r"(dst), "l"(src));
}
#define CP_COMMIT() asm volatile("cp.async.commit_group;" ::: "memory")
#define CP_WAIT0()  asm volatile("cp.async.wait_group 0;" ::: "memory")

// ============================ math helpers ============================
__device__ __forceinline__ float fast_ex2(float x) { float r; asm("ex2.approx.ftz.f32 %0, %1;" : "=f"(r) : "f"(x)); return r; }
__device__ __forceinline__ float fast_rcp(float x) { float r; asm("rcp.approx.ftz.f32 %0, %1;" : "=f"(r) : "f"(x)); return r; }
#define L2E 1.4426950408889634f
__device__ __forceinline__ float sigmoid_f(float x) { return fast_rcp(1.0f + fast_ex2(-x * L2E)); }
__device__ __forceinline__ float tanh_f(float x)    { return 1.0f - 2.0f * fast_rcp(1.0f + fast_ex2(2.0f * x * L2E)); }
__device__ __forceinline__ float selu_f(float x) {
    float e = fast_ex2(x * L2E);
    float neg = 1.6732632423543772f * (e - 1.0f);
    return 1.0507009873554805f * ((x > 0.0f) ? x : neg);
}
__device__ __forceinline__ uint32_t pkbf2(float e0, float e1) {
    uint32_t r; asm("cvt.rn.bf16x2.f32 %0, %1, %2;" : "=r"(r) : "f"(e1), "f"(e0)); return r;
}
__device__ __forceinline__ void qpair_store(char* hiB, char* loB, int elemOff, float e0, float e1) {
    uint32_t h = pkbf2(e0, e1);
    float f0 = __uint_as_float(h << 16);
    float f1 = __uint_as_float(h & 0xffff0000u);
    uint32_t l = pkbf2(e0 - f0, e1 - f1);
    *(uint32_t*)(hiB + elemOff * 2) = h;
    *(uint32_t*)(loB + elemOff * 2) = l;
}

// ============================ prologue kernels ============================
__global__ void scan_kernel(const int* __restrict__ nn, int B) {
    __shared__ int s[1024];
    int tid = threadIdx.x;
    int per = (B + 1023) >> 10;
    if (per > 8) per = 8;
    int base = tid * per;
    int loc[8];
    int sum = 0;
    for (int e = 0; e < per; e++) {
        int idx = base + e;
        int v = (idx < B) ? nn[idx] : 0;
        loc[e] = v; sum += v;
    }
    s[tid] = sum;
    __syncthreads();
    for (int off = 1; off < 1024; off <<= 1) {
        int v = (tid >= off) ? s[tid - off] : 0;
        __syncthreads();
        s[tid] += v;
        __syncthreads();
    }
    int run = s[tid] - sum;
    for (int e = 0; e < per; e++) {
        int idx = base + e;
        if (idx < B) { run += loc[e]; g_cumsum[idx] = run; }
    }
}

__global__ void zero_kernel(int count) {
    int i = blockIdx.x * blockDim.x + threadIdx.x;
    if (i < count) g_pooled[i] = 0.0f;
}

__global__ void quant_w_kernel(const float* __restrict__ w, int kact, int kpad, int stride, int layer) {
    int idx = blockIdx.x * blockDim.x + threadIdx.x;
    if (idx >= 128 * kpad) return;
    int n = idx / kpad, k = idx - n * kpad;
    float v = (k < kact) ? w[k * 128 + n] : 0.0f;
    __nv_bfloat16 hb = __float2bfloat16(v);
    float fh = __bfloat162float(hb);
    __nv_bfloat16 lb = __float2bfloat16(v - fh);
    g_wimg[layer][0][n * stride + k] = hb;
    g_wimg[layer][1][n * stride + k] = lb;
}

// ============================ gemm pieces ============================
__device__ __forceinline__ void prefetch_w(uint32_t sb, uint32_t dstOff, int layer, int half, int bytes) {
    uint32_t dst = sb + dstOff;
    const char* src = (const char*)&g_wimg[layer][half][0];
    int n16 = bytes >> 4;
    for (int i = threadIdx.x; i < n16; i += THREADS)
        cp16(dst + (uint32_t)(i * 16), src + i * 16);
    CP_COMMIT();
}

__device__ __forceinline__ void zero_acc(float acc[2][8][4]) {
#pragma unroll
    for (int a = 0; a < 2; a++)
#pragma unroll
        for (int b = 0; b < 8; b++)
#pragma unroll
            for (int c = 0; c < 4; c++) acc[a][b][c] = 0.0f;
}

// merged pass: (Ah*W + Al*W) sharing B fragments
template <int KSTEPS, int KST>
__device__ __forceinline__ void gemm_pass12(uint32_t aHi, uint32_t aLo, uint32_t wBase,
                                            float acc[2][8][4], int wm, int wn, int lane) {
    uint32_t aOff = (uint32_t)(((wm * 32 + (lane & 15)) * KST + 8 * (lane >> 4)) * 2);
    uint32_t aH = aHi + aOff, aL = aLo + aOff;
    uint32_t bAddr = wBase + (uint32_t)(((wn * 64 + (lane & 7) + 8 * (lane >> 4)) * KST
                                         + 8 * ((lane >> 3) & 1)) * 2);
#pragma unroll
    for (int ks = 0; ks < KSTEPS; ks++) {
        uint32_t b[4][4];
#pragma unroll
        for (int g = 0; g < 4; g++) ldsm4(b[g], bAddr + g * (16 * KST * 2));
        bAddr += 32;
        uint32_t a0[4], a1[4];
        ldsm4(a0, aH); ldsm4(a1, aH + 16 * KST * 2); aH += 32;
#pragma unroll
        for (int g = 0; g < 4; g++) {
            mma16816(acc[0][2 * g],     a0, b[g][0], b[g][1]);
            mma16816(acc[0][2 * g + 1], a0, b[g][2], b[g][3]);
            mma16816(acc[1][2 * g],     a1, b[g][0], b[g][1]);
            mma16816(acc[1][2 * g + 1], a1, b[g][2], b[g][3]);
        }
        ldsm4(a0, aL); ldsm4(a1, aL + 16 * KST * 2); aL += 32;
#pragma unroll
        for (int g = 0; g < 4; g++) {
            mma16816(acc[0][2 * g],     a0, b[g][0], b[g][1]);
            mma16816(acc[0][2 * g + 1], a0, b[g][2], b[g][3]);
            mma16816(acc[1][2 * g],     a1, b[g][0], b[g][1]);
            mma16816(acc[1][2 * g + 1], a1, b[g][2], b[g][3]);
        }
    }
}

// single pass: Ah * Wlo
template <int KSTEPS, int KST>
__device__ __forceinline__ void gemm_pass3(uint32_t aHi, uint32_t wBase,
                                           float acc[2][8][4], int wm, int wn, int lane) {
    uint32_t aAddr = aHi + (uint32_t)(((wm * 32 + (lane & 15)) * KST + 8 * (lane >> 4)) * 2);
    uint32_t bAddr = wBase + (uint32_t)(((wn * 64 + (lane & 7) + 8 * (lane >> 4)) * KST
                                         + 8 * ((lane >> 3) & 1)) * 2);
#pragma unroll
    for (int ks = 0; ks < KSTEPS; ks++) {
        uint32_t a0[4], a1[4], b[4][4];
        ldsm4(a0, aAddr);
        ldsm4(a1, aAddr + 16 * KST * 2);
#pragma unroll
        for (int g = 0; g < 4; g++) ldsm4(b[g], bAddr + g * (16 * KST * 2));
        aAddr += 32; bAddr += 32;
#pragma unroll
        for (int g = 0; g < 4; g++) {
            mma16816(acc[0][2 * g],     a0, b[g][0], b[g][1]);
            mma16816(acc[0][2 * g + 1], a0, b[g][2], b[g][3]);
            mma16816(acc[1][2 * g],     a1, b[g][0], b[g][1]);
            mma16816(acc[1][2 * g + 1], a1, b[g][2], b[g][3]);
        }
    }
}

// ACT 1 = tanh, 2 = selu: bias + act + hi/lo quantize into act tile
template <int ACT>
__device__ __forceinline__ void epilogue_act(float acc[2][8][4], char* sm, int biasIdx,
                                             int wm, int wn, int lane) {
    const float* bias = (const float*)(sm + OFF_BIAS) + biasIdx * 128;
    char* hiB = sm + OFF_ACT;
    char* loB = hiB + ACT_HALF;
    int mb = wm * 32 + (lane >> 2);
#pragma unroll
    for (int nt = 0; nt < 8; nt++) {
        int n = wn * 64 + nt * 8 + 2 * (lane & 3);
        float2 bv = *(const float2*)&bias[n];
#pragma unroll
        for (int mt = 0; mt < 2; mt++)
#pragma unroll
            for (int half = 0; half < 2; half++) {
                int m = mb + mt * 16 + half * 8;
                float x0 = acc[mt][nt][2 * half]     + bv.x;
                float x1 = acc[mt][nt][2 * half + 1] + bv.y;
                x0 = (ACT == 1) ? tanh_f(x0) : selu_f(x0);
                x1 = (ACT == 1) ? tanh_f(x1) : selu_f(x1);
                qpair_store(hiB, loB, m * KST2 + n, x0, x1);
            }
    }
}

// ============================ fused main kernel ============================
__global__ void __launch_bounds__(THREADS, 1)
fused_kernel(const float* __restrict__ nodes, const float* __restrict__ nmask,
             const float* __restrict__ i1b, const float* __restrict__ i2b,
             const float* __restrict__ j1b, const float* __restrict__ j2b,
             int N, int B) {
    extern __shared__ char sm[];
    uint32_t sb = smem_u32(sm);
    int tid = threadIdx.x;
    int lane = tid & 31, wid = tid >> 5;
    int wm = wid & 3, wn = wid >> 2;

    float* biasS = (float*)(sm + OFF_BIAS);
    int*   gidxS = (int*)(sm + OFF_GIDX);
    float* maskS = (float*)(sm + OFF_MASK);

    // start loading Wi1-hi immediately; overlap with hx quantize below
    prefetch_w(sb, OFF_W0, 0, 0, W1_BYTES);

    // biases
    for (int i = tid; i < 512; i += THREADS) {
        const float* bp = (i < 128) ? i1b : (i < 256) ? i2b : (i < 384) ? j1b : j2b;
        biasS[i] = bp[i & 127];
    }
    // mask + graph index
    if (tid < 128) {
        int gn = blockIdx.x * TILE_M + tid;
        maskS[tid] = (gn < N) ? nmask[gn] : 0.0f;
        int lo = 0, hi = B - 1;
        while (lo < hi) {
            int mid = (lo + hi) >> 1;
            if (gn < g_cumsum[mid]) hi = mid; else lo = mid + 1;
        }
        gidxS[tid] = lo;
    }

    // ---- load + quantize hx tile [128 x 80] (hi/lo) ----
    {
        int m = tid & 127, h = tid >> 7;
        int gn = blockIdx.x * TILE_M + m;
        char* hiB = sm + OFF_HX;
        char* loB = hiB + HX_HALF;
        float xv[32];
        if (gn < N) {
#pragma unroll
            for (int q = 0; q < 8; q++)
                ((float4*)xv)[q] = *(const float4*)&nodes[(size_t)gn * 64 + h * 32 + q * 4];
        } else {
#pragma unroll
            for (int i = 0; i < 32; i++) xv[i] = 0.0f;
        }
#pragma unroll
        for (int p = 0; p < 16; p++)
            qpair_store(hiB, loB, m * KST1 + h * 32 + 2 * p, xv[2 * p], xv[2 * p + 1]);
        if (h == 1) {
            float e0 = 0.0f, e1 = 0.0f;
            if (gn < N) { e0 = nodes[(size_t)gn * 64]; e1 = nodes[(size_t)gn * 64 + 1]; }
            qpair_store(hiB, loB, m * KST1 + 64, e0, e1);
#pragma unroll
            for (int k = 66; k < 80; k += 2)
                qpair_store(hiB, loB, m * KST1 + k, 0.0f, 0.0f);
        }
    }

    uint32_t hxHi = sb + OFF_HX, hxLo = hxHi + HX_HALF;
    uint32_t acHi = sb + OFF_ACT, acLo = acHi + ACT_HALF;
    uint32_t w0 = sb + OFF_W0, w1 = sb + OFF_W1;

    CP_WAIT0();
    __syncthreads();

    float acc[2][8][4];
    float ri[2][8][4];   // i2 output (+bias) kept in registers

    // ===== G1: i layer-1 =====
    prefetch_w(sb, OFF_W1, 0, 1, W1_BYTES);                    // Wi1-lo -> W1
    zero_acc(acc);
    gemm_pass12<KSTEPS1, KST1>(hxHi, hxLo, w0, acc, wm, wn, lane);
    CP_WAIT0(); __syncthreads();
    prefetch_w(sb, OFF_W0, 1, 0, W2_BYTES);                    // Wi2-hi -> W0
    gemm_pass3<KSTEPS1, KST1>(hxHi, w1, acc, wm, wn, lane);
    epilogue_act<1>(acc, sm, 0, wm, wn, lane);
    CP_WAIT0(); __syncthreads();

    // ===== G2: i layer-2 (result -> registers) =====
    prefetch_w(sb, OFF_W1, 1, 1, W2_BYTES);                    // Wi2-lo -> W1
    zero_acc(acc);
    gemm_pass12<KSTEPS2, KST2>(acHi, acLo, w0, acc, wm, wn, lane);
    CP_WAIT0(); __syncthreads();
    prefetch_w(sb, OFF_W0, 2, 0, W1_BYTES);                    // Wj1-hi -> W0
    gemm_pass3<KSTEPS2, KST2>(acHi, w1, acc, wm, wn, lane);
    {
        const float* bias = biasS + 1 * 128;
#pragma unroll
        for (int nt = 0; nt < 8; nt++) {
            int n = wn * 64 + nt * 8 + 2 * (lane & 3);
            float2 bv = *(const float2*)&bias[n];
#pragma unroll
            for (int mt = 0; mt < 2; mt++) {
                ri[mt][nt][0] = acc[mt][nt][0] + bv.x;
                ri[mt][nt][1] = acc[mt][nt][1] + bv.y;
                ri[mt][nt][2] = acc[mt][nt][2] + bv.x;
                ri[mt][nt][3] = acc[mt][nt][3] + bv.y;
            }
        }
    }
    CP_WAIT0(); __syncthreads();

    // ===== G3: j layer-1 =====
    prefetch_w(sb, OFF_W1, 2, 1, W1_BYTES);                    // Wj1-lo -> W1
    zero_acc(acc);
    gemm_pass12<KSTEPS1, KST1>(hxHi, hxLo, w0, acc, wm, wn, lane);
    CP_WAIT0(); __syncthreads();
    prefetch_w(sb, OFF_W0, 3, 0, W2_BYTES);                    // Wj2-hi -> W0
    gemm_pass3<KSTEPS1, KST1>(hxHi, w1, acc, wm, wn, lane);
    epilogue_act<2>(acc, sm, 2, wm, wn, lane);                 // overwrites act tile
    CP_WAIT0(); __syncthreads();

    // ===== G4: j layer-2 =====
    prefetch_w(sb, OFF_W1, 3, 1, W2_BYTES);                    // Wj2-lo -> W1
    zero_acc(acc);
    gemm_pass12<KSTEPS2, KST2>(acHi, acLo, w0, acc, wm, wn, lane);
    CP_WAIT0(); __syncthreads();
    gemm_pass3<KSTEPS2, KST2>(acHi, w1, acc, wm, wn, lane);
    __syncthreads();   // all warps done reading act tile before RR overlays it

    // ---- gate in registers, write RR over act region ----
    {
        const float* bias = biasS + 3 * 128;
        float* RR = (float*)(sm + OFF_ACT);
        int mb = wm * 32 + (lane >> 2);
#pragma unroll
        for (int nt = 0; nt < 8; nt++) {
            int n = wn * 64 + nt * 8 + 2 * (lane & 3);
            float2 bv = *(const float2*)&bias[n];
#pragma unroll
            for (int mt = 0; mt < 2; mt++)
#pragma unroll
                for (int half = 0; half < 2; half++) {
                    int m = mb + mt * 16 + half * 8;
                    float mk = maskS[m];
                    float2 o;
                    o.x = sigmoid_f(ri[mt][nt][2 * half])     * (acc[mt][nt][2 * half]     + bv.x) * mk;
                    o.y = sigmoid_f(ri[mt][nt][2 * half + 1]) * (acc[mt][nt][2 * half + 1] + bv.y) * mk;
                    *(float2*)&RR[m * I2ST + n] = o;
                }
        }
    }
    __syncthreads();

    // ---- segmented column sum -> atomicAdd ----
    {
        const float* RR = (const float*)(sm + OFF_ACT);
        int c = tid & 127;
        int h = tid >> 7;
        int m0 = h * 64;
        float cs = 0.0f;
        int gcur = gidxS[m0];
        for (int mm = m0; mm < m0 + 64; mm++) {
            float r = RR[mm * I2ST + c];
            int g = gidxS[mm];
            if (g != gcur) { atomicAdd(&g_pooled[gcur * RN + c], cs); cs = 0.0f; gcur = g; }
            cs += r;
        }
        atomicAdd(&g_pooled[gcur * RN + c], cs);
    }
}

// ============================ final per-graph MLP ============================
__global__ void final_kernel(const float* __restrict__ h1w, const float* __restrict__ h1b,
                             const float* __restrict__ h2w, const float* __restrict__ h2b,
                             float* __restrict__ out, int B) {
    int g = blockIdx.x * (blockDim.x >> 5) + (threadIdx.x >> 5);
    int lane = threadIdx.x & 31;
    if (g >= B) return;
    const float* pr = &g_pooled[g * RN];
    float4 bv = ((const float4*)h1b)[lane];
    float a0 = bv.x, a1 = bv.y, a2 = bv.z, a3 = bv.w;
#pragma unroll 4
    for (int k = 0; k < RN; k++) {
        float pv = pr[k];
        float4 wv = *(const float4*)(h1w + k * RN + (lane << 2));
        a0 = fmaf(pv, wv.x, a0);
        a1 = fmaf(pv, wv.y, a1);
        a2 = fmaf(pv, wv.z, a2);
        a3 = fmaf(pv, wv.w, a3);
    }
    a0 = selu_f(a0); a1 = selu_f(a1); a2 = selu_f(a2); a3 = selu_f(a3);
    float4 h2 = ((const float4*)h2w)[lane];
    float part = a0 * h2.x + a1 * h2.y + a2 * h2.z + a3 * h2.w;
#pragma unroll
    for (int off = 16; off > 0; off >>= 1)
        part += __shfl_down_sync(0xffffffffu, part, off);
    if (lane == 0) out[g] = part + h2b[0];
}

// ============================ launch ============================
extern "C" void kernel_launch(void* const* d_in, const int* in_sizes, int n_in,
                              void* d_out, int out_size) {
    const float* nodes = (const float*)d_in[0];
    const float* nmask = (const float*)d_in[1];
    const int*   n_node = (const int*)d_in[2];
    const float* i1w = (const float*)d_in[3];
    const float* i1b = (const float*)d_in[4];
    const float* i2w = (const float*)d_in[5];
    const float* i2b = (const float*)d_in[6];
    const float* j1w = (const float*)d_in[7];
    const float* j1b = (const float*)d_in[8];
    const float* j2w = (const float*)d_in[9];
    const float* j2b = (const float*)d_in[10];
    const float* h1w = (const float*)d_in[11];
    const float* h1b = (const float*)d_in[12];
    const float* h2w = (const float*)d_in[13];
    const float* h2b = (const float*)d_in[14];

    int N = in_sizes[1];
    int B = in_sizes[2];

    scan_kernel<<<1, 1024>>>(n_node, B);

    int pc = B * RN;
    zero_kernel<<<(pc + 255) / 256, 256>>>(pc);

    quant_w_kernel<<<(128 * 80 + 255) / 256, 256>>>(i1w, 66, 80, KST1, 0);
    quant_w_kernel<<<(128 * 128 + 255) / 256, 256>>>(i2w, 128, 128, KST2, 1);
    quant_w_kernel<<<(128 * 80 + 255) / 256, 256>>>(j1w, 66, 80, KST1, 2);
    quant_w_kernel<<<(128 * 128 + 255) / 256, 256>>>(j2w, 128, 128, KST2, 3);

    cudaFuncSetAttribute(fused_kernel, cudaFuncAttributeMaxDynamicSharedMemorySize, SMEM_SZ);
    int grid = (N + TILE_M - 1) / TILE_M;
    fused_kernel<<<grid, THREADS, SMEM_SZ>>>(nodes, nmask, i1b, i2b, j1b, j2b, N, B);

    final_kernel<<<(B + 7) / 8, 256>>>(h1w, h1b, h2w, h2b, (float*)d_out, B);
}